// round 8
// baseline (speedup 1.0000x reference)
#include <cuda_runtime.h>
#include <math_constants.h>
#include <cstdint>

#define BB 32
#define HH 12
#define LL 512
#define DD 768
#define HD 64
#define KSEL 255
#define KOUT 256

#define OUT_MASK_OFF ((size_t)BB * KOUT * DD)
#define OUT_TOME_OFF (OUT_MASK_OFF + (size_t)BB * KOUT)

// ---------------- scratch ----------------
__device__ float g_imp[BB * LL];
__device__ float g_att[BB * LL];
__device__ int   g_idx[BB * KSEL];
__device__ float g_sent[BB * DD];
__device__ float g_kbias[BB * HH];
__device__ float g_wke[BB * HH * DD];
__device__ float g_w[BB * HH * LL];
__device__ float g_hv[BB * HH * DD];
__device__ float g_ctx[BB * DD];

// ---------------- 1: prologue — zero accumulators, tome/mask constants, att softmax
__global__ void k_prologue(const float* __restrict__ am, float* __restrict__ out) {
    const int t = threadIdx.x;
    const int b = blockIdx.x;
    const int gid = b * 512 + t;
    const int nthr = 64 * 512;

    for (int i = gid; i < BB * LL; i += nthr) g_imp[i] = 0.f;
    for (int i = gid; i < BB * DD; i += nthr) g_sent[i] = 0.f;
    for (int i = gid; i < BB * HH * DD; i += nthr) g_hv[i] = 0.f;
    for (int i = gid; i < BB * KOUT; i += nthr) out[OUT_TOME_OFF + i] = 1.f;
    if (gid < BB) out[OUT_MASK_OFF + (size_t)gid * KOUT + KSEL] = 0.f;

    if (b < BB) {
        __shared__ float red[LL];
        const float amv = am[b * LL + t];
        red[t] = amv;
        __syncthreads();
        for (int s = 256; s > 0; s >>= 1) {
            if (t < s) red[t] = fmaxf(red[t], red[t + s]);
            __syncthreads();
        }
        const float m = red[0];
        __syncthreads();
        const float e = __expf(amv - m);
        red[t] = e;
        __syncthreads();
        for (int s = 256; s > 0; s >>= 1) {
            if (t < s) red[t] += red[t + s];
            __syncthreads();
        }
        g_att[b * LL + t] = e / red[0];
    }
}

// ---------------- 2: sentences[b,d] += sum_{l chunk} att*hidden  (grid 6,8,B x128)
__global__ void k_sentence(const float* __restrict__ hidden) {
    const int t  = threadIdx.x;
    const int dc = blockIdx.x;
    const int lc = blockIdx.y;
    const int b  = blockIdx.z;
    __shared__ float s_att[64];
    if (t < 64) s_att[t] = g_att[b * LL + lc * 64 + t];
    __syncthreads();

    const float* hp = hidden + ((size_t)b * LL + lc * 64) * DD + dc * 128 + t;
    float acc = 0.f;
#pragma unroll 16
    for (int l = 0; l < 64; l++) acc += s_att[l] * hp[(size_t)l * DD];
    atomicAdd(&g_sent[b * DD + dc * 128 + t], acc);
}

// ---------------- 3: fused q-projection + effective-key  (grid (H,B) x512)
__global__ void k_qk(const float* __restrict__ Wq, const float* __restrict__ bq,
                     const float* __restrict__ Wk, const float* __restrict__ bk) {
    const int t = threadIdx.x;
    const int h = blockIdx.x;
    const int b = blockIdx.y;
    __shared__ float s_sent[DD];
    __shared__ float s_part[8][HD];
    __shared__ float s_qh[HD];

    for (int i = t; i < DD; i += 512) s_sent[i] = g_sent[b * DD + i];
    __syncthreads();

    const int jg = t >> 6;
    const int d  = t & 63;
    {
        float acc = 0.f;
        const float* wp = Wq + h * HD + d;
#pragma unroll 8
        for (int j = jg * 96; j < jg * 96 + 96; j++)
            acc += s_sent[j] * wp[(size_t)j * DD];
        s_part[jg][d] = acc;
    }
    __syncthreads();
    if (t < HD) {
        float q = bq[h * HD + t];
#pragma unroll
        for (int g = 0; g < 8; g++) q += s_part[g][t];
        s_qh[t] = q;
    }
    __syncthreads();

    if (t < 32) {
        float kb = s_qh[t] * bk[h * HD + t] + s_qh[t + 32] * bk[h * HD + t + 32];
#pragma unroll
        for (int off = 16; off; off >>= 1) kb += __shfl_down_sync(0xffffffffu, kb, off);
        if (t == 0) g_kbias[b * HH + h] = kb;
    }

    const int w = t >> 5, lane = t & 31;
    const float qa = s_qh[lane], qb = s_qh[lane + 32];
    for (int j = w * 48; j < w * 48 + 48; j++) {
        const float* wp = Wk + (size_t)j * DD + h * HD;
        float a = wp[lane] * qa + wp[lane + 32] * qb;
#pragma unroll
        for (int off = 16; off; off >>= 1) a += __shfl_down_sync(0xffffffffu, a, off);
        if (lane == 0) g_wke[((size_t)b * HH + h) * DD + j] = a;
    }
}

// ---------------- 4: logits (PROFILED)  grid (32,B) x384 — float4 LDS
__global__ void k_logits(const float* __restrict__ hidden, const float* __restrict__ am) {
    const int t = threadIdx.x;
    const int b = blockIdx.y;
    const int l0 = blockIdx.x * 16;
    __shared__ float s_h[16 * DD];   // 48 KB
    __shared__ float skb[HH];

    {
        const float4* src = (const float4*)(hidden + ((size_t)b * LL + l0) * DD);
        float4* dst = (float4*)s_h;
#pragma unroll
        for (int i = t; i < 16 * DD / 4; i += 384) dst[i] = src[i];
    }
    if (t < HH) skb[t] = g_kbias[b * HH + t];

    const int h = t >> 5, lane = t & 31;
    float4 wk[6];
    {
        const float4* wkp = (const float4*)(g_wke + ((size_t)b * HH + h) * DD) + lane;
#pragma unroll
        for (int j = 0; j < 6; j++) wk[j] = wkp[32 * j];
    }
    __syncthreads();

    float acc[16];
#pragma unroll
    for (int li = 0; li < 16; li++) {
        const float4* hp = (const float4*)(s_h + li * DD) + lane;
        float a = 0.f;
#pragma unroll
        for (int j = 0; j < 6; j++) {
            float4 v = hp[32 * j];
            a += v.x * wk[j].x + v.y * wk[j].y + v.z * wk[j].z + v.w * wk[j].w;
        }
        acc[li] = a;
    }
#pragma unroll
    for (int li = 0; li < 16; li++) {
        float a = acc[li];
#pragma unroll
        for (int off = 16; off; off >>= 1) a += __shfl_down_sync(0xffffffffu, a, off);
        if (lane == 0) {
            const int l = l0 + li;
            const float amv = am[b * LL + l];
            g_w[((size_t)b * HH + h) * LL + l] =
                (amv < -10.f) ? -CUDART_INF_F : (a + skb[h]) * 0.125f;
        }
    }
}

// ---------------- 5: softmax over l, in place. grid (B*H) x512
__global__ void k_softmax_w() {
    const int t = threadIdx.x;
    const int bh = blockIdx.x;
    __shared__ float red[LL];
    const float v = g_w[(size_t)bh * LL + t];
    red[t] = v;
    __syncthreads();
    for (int s = 256; s > 0; s >>= 1) {
        if (t < s) red[t] = fmaxf(red[t], red[t + s]);
        __syncthreads();
    }
    const float m = red[0];
    __syncthreads();
    const float e = __expf(v - m);
    red[t] = e;
    __syncthreads();
    for (int s = 256; s > 0; s >>= 1) {
        if (t < s) red[t] += red[t + s];
        __syncthreads();
    }
    g_w[(size_t)bh * LL + t] = e / red[0];
}

// ---------------- 6: hv[b,h,d] += sum_{l chunk} w*hidden  (grid 6,8,B x128)
__global__ void k_hv(const float* __restrict__ hidden) {
    const int t  = threadIdx.x;
    const int dc = blockIdx.x;
    const int lc = blockIdx.y;
    const int b  = blockIdx.z;
    __shared__ float sw[HH * 64];
    for (int i = t; i < HH * 64; i += 128) {
        const int h = i >> 6, l = i & 63;
        sw[i] = g_w[((size_t)b * HH + h) * LL + lc * 64 + l];
    }
    __syncthreads();

    float acc[HH];
#pragma unroll
    for (int h = 0; h < HH; h++) acc[h] = 0.f;

    const float* hp = hidden + ((size_t)b * LL + lc * 64) * DD + dc * 128 + t;
#pragma unroll 4
    for (int l = 0; l < 64; l++) {
        const float hval = hp[(size_t)l * DD];
#pragma unroll
        for (int h = 0; h < HH; h++) acc[h] += sw[h * 64 + l] * hval;
    }
#pragma unroll
    for (int h = 0; h < HH; h++)
        atomicAdd(&g_hv[((size_t)b * HH + h) * DD + dc * 128 + t], acc[h]);
}

// ---------------- 7: ctx[b, h*64+d] = hv[b,h]·Wv[:, h-slice] + bv  (grid (H,B) x512)
__global__ void k_ctx(const float* __restrict__ Wv, const float* __restrict__ bv) {
    const int t = threadIdx.x;
    const int h = blockIdx.x;
    const int b = blockIdx.y;
    __shared__ float sh[DD];
    __shared__ float s_part[8][HD];
    for (int i = t; i < DD; i += 512) sh[i] = g_hv[((size_t)b * HH + h) * DD + i];
    __syncthreads();

    const int jg = t >> 6;
    const int d  = t & 63;
    float acc = 0.f;
    const float* wp = Wv + h * HD + d;
#pragma unroll 8
    for (int j = jg * 96; j < jg * 96 + 96; j++)
        acc += sh[j] * wp[(size_t)j * DD];
    s_part[jg][d] = acc;
    __syncthreads();
    if (t < HD) {
        float c = bv[h * HD + t];
#pragma unroll
        for (int g = 0; g < 8; g++) c += s_part[g][t];
        g_ctx[b * DD + h * HD + t] = c;
    }
}

// ---------------- 8: new_token = ctx @ Wo + bo  (grid (6,B) x512)
__global__ void k_newtok(const float* __restrict__ Wo, const float* __restrict__ bo,
                         float* __restrict__ out) {
    const int t  = threadIdx.x;
    const int dc = blockIdx.x;
    const int b  = blockIdx.y;
    __shared__ float sc[DD];
    __shared__ float s_part[4][128];
    for (int i = t; i < DD; i += 512) sc[i] = g_ctx[b * DD + i];
    __syncthreads();

    const int jg = t >> 7;
    const int d  = t & 127;
    float acc = 0.f;
    const float* wp = Wo + dc * 128 + d;
#pragma unroll 8
    for (int j = jg * 192; j < jg * 192 + 192; j++)
        acc += sc[j] * wp[(size_t)j * DD];
    s_part[jg][d] = acc;
    __syncthreads();
    if (t < 128) {
        float o = bo[dc * 128 + t] + s_part[0][t] + s_part[1][t] + s_part[2][t] + s_part[3][t];
        out[((size_t)b * KOUT + KSEL) * DD + dc * 128 + t] = o;
    }
}

// ---------------- 9: column-sum of scores (402 MB) grid B*H*4 x256
__global__ void k_reduce_scores(const float* __restrict__ scores,
                                const float* __restrict__ am) {
    const int t   = threadIdx.x;
    const int blk = blockIdx.x;
    const int qc  = blk & 3;
    const int bh  = blk >> 2;
    const int b   = bh / HH;

    __shared__ float s_af[128];
    const int q0 = qc * 128;
    if (t < 128) {
        float amv = am[b * LL + q0 + t];
        s_af[t] = (amv > -10.f) ? 1.f : 0.f;
    }
    __syncthreads();

    const int tq  = t >> 7;
    const int col = t & 127;
    const float4* base =
        (const float4*)(scores + ((size_t)bh * LL + q0 + tq * 64) * LL) + col;
    const float* af = s_af + tq * 64;

    float4 a0 = make_float4(0.f, 0.f, 0.f, 0.f);
#pragma unroll 8
    for (int q = 0; q < 64; q++) {
        const float f = af[q];
        float4 v = __ldcs(base + (size_t)q * (LL / 4));
        a0.x += f * v.x; a0.y += f * v.y;
        a0.z += f * v.z; a0.w += f * v.w;
    }
    float* dst = &g_imp[b * LL + col * 4];
    atomicAdd(dst + 0, a0.x);
    atomicAdd(dst + 1, a0.y);
    atomicAdd(dst + 2, a0.z);
    atomicAdd(dst + 3, a0.w);
}

// ---------------- 10: top-K (exact stable rank + scan)  grid B x512
__global__ void k_topk(const float* __restrict__ am) {
    const int t = threadIdx.x;
    const int b = blockIdx.x;

    __shared__ float sv[LL];
    __shared__ int   ssc[LL];

    const float amv = am[b * LL + t];
    const float afl = (amv > -10.f) ? 1.f : 0.f;
    float v = g_imp[b * LL + t] * afl * (1.0f / (HH * LL));
    if (t == 0) v = CUDART_INF_F;
    sv[t] = v;
    __syncthreads();

    int rank = 0;
#pragma unroll 8
    for (int j = 0; j < LL; j++) {
        float vj = sv[j];
        rank += (vj > v) || (vj == v && j < t);
    }
    const int sel = (rank < KSEL) ? 1 : 0;

    ssc[t] = sel;
    __syncthreads();
    for (int off = 1; off < LL; off <<= 1) {
        int y = (t >= off) ? ssc[t - off] : 0;
        __syncthreads();
        ssc[t] += y;
        __syncthreads();
    }
    if (sel) g_idx[b * KSEL + (ssc[t] - 1)] = t;
}

// ---------------- 11: gather preserved rows + mask  grid (KSEL,B) x192
__global__ void k_gather(const float* __restrict__ hidden, const float* __restrict__ am,
                         float* __restrict__ out) {
    const int t = threadIdx.x;
    const int k = blockIdx.x;
    const int b = blockIdx.y;
    const int idx = g_idx[b * KSEL + k];
    const float4* src = (const float4*)(hidden + ((size_t)b * LL + idx) * DD);
    float4* dst = (float4*)(out + ((size_t)b * KOUT + k) * DD);
    dst[t] = src[t];
    if (t == 0) {
        out[OUT_MASK_OFF + (size_t)b * KOUT + k] = am[b * LL + idx];
    }
}

// ---------------- launcher with fork-join overlap ----------------
extern "C" void kernel_launch(void* const* d_in, const int* in_sizes, int n_in,
                              void* d_out, int out_size) {
    const float* hidden = (const float*)d_in[0];
    const float* am     = (const float*)d_in[1];
    const float* scores = (const float*)d_in[2];
    const float* Wq     = (const float*)d_in[3];
    const float* bq     = (const float*)d_in[4];
    const float* Wk     = (const float*)d_in[5];
    const float* bk     = (const float*)d_in[6];
    const float* Wv     = (const float*)d_in[7];
    const float* bv     = (const float*)d_in[8];
    const float* Wo     = (const float*)d_in[9];
    const float* bo     = (const float*)d_in[10];
    float* out = (float*)d_out;

    // one-time creation (first call is the uncaptured correctness run)
    static cudaStream_t s2 = nullptr;
    static cudaEvent_t ev_fork = nullptr, ev_join = nullptr;
    if (s2 == nullptr) {
        cudaStreamCreateWithFlags(&s2, cudaStreamNonBlocking);
        cudaEventCreateWithFlags(&ev_fork, cudaEventDisableTiming);
        cudaEventCreateWithFlags(&ev_join, cudaEventDisableTiming);
    }

    k_prologue<<<64, 512>>>(am, out);                           // #1 (capture stream)

    // main chain (capture stream)
    {
        dim3 g(6, 8, BB);
        k_sentence<<<g, 128>>>(hidden);                         // #2
    }
    {
        dim3 g(HH, BB);
        k_qk<<<g, 512>>>(Wq, bq, Wk, bk);                       // #3
    }
    {
        dim3 g(32, BB);
        k_logits<<<g, 384>>>(hidden, am);                       // #4 (profiled)
    }
    k_softmax_w<<<BB * HH, 512>>>();                            // #5
    {
        dim3 g(6, 8, BB);
        k_hv<<<g, 128>>>(hidden);                               // #6
    }
    {
        dim3 g(HH, BB);
        k_ctx<<<g, 512>>>(Wv, bv);                              // #7
    }
    {
        dim3 g(6, BB);
        k_newtok<<<g, 512>>>(Wo, bo, out);                      // #8
    }

    // fork: importance branch depends only on prologue (g_imp zeroed)
    cudaEventRecord(ev_fork, 0);
    cudaStreamWaitEvent(s2, ev_fork, 0);
    k_reduce_scores<<<BB * HH * 4, 256, 0, s2>>>(scores, am);   // #9 (s2)
    k_topk<<<BB, 512, 0, s2>>>(am);                             // #10 (s2)
    {
        dim3 g(KSEL, BB);
        k_gather<<<g, 192, 0, s2>>>(hidden, am, out);           // #11 (s2)
    }
    cudaEventRecord(ev_join, s2);
    cudaStreamWaitEvent(0, ev_join, 0);
}

// round 9
// speedup vs baseline: 1.2078x; 1.2078x over previous
#include <cuda_runtime.h>
#include <math_constants.h>
#include <cstdint>

#define BB 32
#define HH 12
#define LL 512
#define DD 768
#define HD 64
#define KSEL 255
#define KOUT 256

#define OUT_MASK_OFF ((size_t)BB * KOUT * DD)
#define OUT_TOME_OFF (OUT_MASK_OFF + (size_t)BB * KOUT)

// ---------------- scratch ----------------
__device__ float g_imp[BB * LL];
__device__ float g_att[BB * LL];
__device__ int   g_idx[BB * KSEL];
__device__ float g_sent[BB * DD];
__device__ float g_kbias[BB * HH];
__device__ float g_wke[BB * HH * DD];
__device__ float g_w[BB * HH * LL];
__device__ float g_hv[BB * HH * DD];
__device__ float g_ctx[BB * DD];

// ---------------- 1: prologue — zero accumulators, tome/mask constants, att softmax
__global__ void k_prologue(const float* __restrict__ am, float* __restrict__ out) {
    const int t = threadIdx.x;
    const int b = blockIdx.x;
    const int gid = b * 512 + t;
    const int nthr = 64 * 512;

    for (int i = gid; i < BB * LL; i += nthr) g_imp[i] = 0.f;
    for (int i = gid; i < BB * DD; i += nthr) g_sent[i] = 0.f;
    for (int i = gid; i < BB * HH * DD; i += nthr) g_hv[i] = 0.f;
    for (int i = gid; i < BB * KOUT; i += nthr) out[OUT_TOME_OFF + i] = 1.f;
    if (gid < BB) out[OUT_MASK_OFF + (size_t)gid * KOUT + KSEL] = 0.f;

    if (b < BB) {
        __shared__ float red[LL];
        const float amv = am[b * LL + t];
        red[t] = amv;
        __syncthreads();
        for (int s = 256; s > 0; s >>= 1) {
            if (t < s) red[t] = fmaxf(red[t], red[t + s]);
            __syncthreads();
        }
        const float m = red[0];
        __syncthreads();
        const float e = __expf(amv - m);
        red[t] = e;
        __syncthreads();
        for (int s = 256; s > 0; s >>= 1) {
            if (t < s) red[t] += red[t + s];
            __syncthreads();
        }
        g_att[b * LL + t] = e / red[0];
    }
}

// ---------------- 2: sentences[b,d] += sum_{l chunk} att*hidden  (grid 6,8,B x128)
__global__ void k_sentence(const float* __restrict__ hidden) {
    const int t  = threadIdx.x;
    const int dc = blockIdx.x;
    const int lc = blockIdx.y;
    const int b  = blockIdx.z;
    __shared__ float s_att[64];
    if (t < 64) s_att[t] = g_att[b * LL + lc * 64 + t];
    __syncthreads();

    const float* hp = hidden + ((size_t)b * LL + lc * 64) * DD + dc * 128 + t;
    float acc = 0.f;
#pragma unroll 16
    for (int l = 0; l < 64; l++) acc += s_att[l] * hp[(size_t)l * DD];
    atomicAdd(&g_sent[b * DD + dc * 128 + t], acc);
}

// ---------------- 3: fused q-projection + effective-key  (grid (H,B) x512)
__global__ void k_qk(const float* __restrict__ Wq, const float* __restrict__ bq,
                     const float* __restrict__ Wk, const float* __restrict__ bk) {
    const int t = threadIdx.x;
    const int h = blockIdx.x;
    const int b = blockIdx.y;
    __shared__ float s_sent[DD];
    __shared__ float s_part[8][HD];
    __shared__ float s_qh[HD];

    for (int i = t; i < DD; i += 512) s_sent[i] = g_sent[b * DD + i];
    __syncthreads();

    const int jg = t >> 6;
    const int d  = t & 63;
    {
        float acc = 0.f;
        const float* wp = Wq + h * HD + d;
#pragma unroll 8
        for (int j = jg * 96; j < jg * 96 + 96; j++)
            acc += s_sent[j] * wp[(size_t)j * DD];
        s_part[jg][d] = acc;
    }
    __syncthreads();
    if (t < HD) {
        float q = bq[h * HD + t];
#pragma unroll
        for (int g = 0; g < 8; g++) q += s_part[g][t];
        s_qh[t] = q;
    }
    __syncthreads();

    if (t < 32) {
        float kb = s_qh[t] * bk[h * HD + t] + s_qh[t + 32] * bk[h * HD + t + 32];
#pragma unroll
        for (int off = 16; off; off >>= 1) kb += __shfl_down_sync(0xffffffffu, kb, off);
        if (t == 0) g_kbias[b * HH + h] = kb;
    }

    const int w = t >> 5, lane = t & 31;
    const float qa = s_qh[lane], qb = s_qh[lane + 32];
    for (int j = w * 48; j < w * 48 + 48; j++) {
        const float* wp = Wk + (size_t)j * DD + h * HD;
        float a = wp[lane] * qa + wp[lane + 32] * qb;
#pragma unroll
        for (int off = 16; off; off >>= 1) a += __shfl_down_sync(0xffffffffu, a, off);
        if (lane == 0) g_wke[((size_t)b * HH + h) * DD + j] = a;
    }
}

// ---------------- 4: logits (PROFILED)  grid (32,B) x384 — scalar LDS (R7 form)
__global__ void k_logits(const float* __restrict__ hidden, const float* __restrict__ am) {
    const int t = threadIdx.x;
    const int b = blockIdx.y;
    const int l0 = blockIdx.x * 16;
    __shared__ float s_h[16 * DD];   // 48 KB
    __shared__ float skb[HH];

    {
        const float4* src = (const float4*)(hidden + ((size_t)b * LL + l0) * DD);
        float4* dst = (float4*)s_h;
#pragma unroll
        for (int i = t; i < 16 * DD / 4; i += 384) dst[i] = src[i];
    }
    if (t < HH) skb[t] = g_kbias[b * HH + t];

    const int h = t >> 5, lane = t & 31;
    float wk[24];
    {
        const float* wkp = g_wke + ((size_t)b * HH + h) * DD + lane;
#pragma unroll
        for (int j = 0; j < 24; j++) wk[j] = wkp[32 * j];
    }
    __syncthreads();

    float acc[16];
#pragma unroll
    for (int li = 0; li < 16; li++) {
        const float* hp = s_h + li * DD + lane;
        float a = 0.f;
#pragma unroll
        for (int j = 0; j < 24; j++) a += hp[32 * j] * wk[j];
        acc[li] = a;
    }
#pragma unroll
    for (int li = 0; li < 16; li++) {
        float a = acc[li];
#pragma unroll
        for (int off = 16; off; off >>= 1) a += __shfl_down_sync(0xffffffffu, a, off);
        if (lane == 0) {
            const int l = l0 + li;
            const float amv = am[b * LL + l];
            g_w[((size_t)b * HH + h) * LL + l] =
                (amv < -10.f) ? -CUDART_INF_F : (a + skb[h]) * 0.125f;
        }
    }
}

// ---------------- 5: softmax over l, in place. grid (B*H) x512
__global__ void k_softmax_w() {
    const int t = threadIdx.x;
    const int bh = blockIdx.x;
    __shared__ float red[LL];
    const float v = g_w[(size_t)bh * LL + t];
    red[t] = v;
    __syncthreads();
    for (int s = 256; s > 0; s >>= 1) {
        if (t < s) red[t] = fmaxf(red[t], red[t + s]);
        __syncthreads();
    }
    const float m = red[0];
    __syncthreads();
    const float e = __expf(v - m);
    red[t] = e;
    __syncthreads();
    for (int s = 256; s > 0; s >>= 1) {
        if (t < s) red[t] += red[t + s];
        __syncthreads();
    }
    g_w[(size_t)bh * LL + t] = e / red[0];
}

// ---------------- 6: hv[b,h,d] += sum_{l chunk} w*hidden  (grid 6,8,B x128)
__global__ void k_hv(const float* __restrict__ hidden) {
    const int t  = threadIdx.x;
    const int dc = blockIdx.x;
    const int lc = blockIdx.y;
    const int b  = blockIdx.z;
    __shared__ float sw[HH * 64];
    for (int i = t; i < HH * 64; i += 128) {
        const int h = i >> 6, l = i & 63;
        sw[i] = g_w[((size_t)b * HH + h) * LL + lc * 64 + l];
    }
    __syncthreads();

    float acc[HH];
#pragma unroll
    for (int h = 0; h < HH; h++) acc[h] = 0.f;

    const float* hp = hidden + ((size_t)b * LL + lc * 64) * DD + dc * 128 + t;
#pragma unroll 4
    for (int l = 0; l < 64; l++) {
        const float hval = hp[(size_t)l * DD];
#pragma unroll
        for (int h = 0; h < HH; h++) acc[h] += sw[h * 64 + l] * hval;
    }
#pragma unroll
    for (int h = 0; h < HH; h++)
        atomicAdd(&g_hv[((size_t)b * HH + h) * DD + dc * 128 + t], acc[h]);
}

// ---------------- 7: ctx[b, h*64+d] = hv[b,h]·Wv[:, h-slice] + bv  (grid (H,B) x512)
__global__ void k_ctx(const float* __restrict__ Wv, const float* __restrict__ bv) {
    const int t = threadIdx.x;
    const int h = blockIdx.x;
    const int b = blockIdx.y;
    __shared__ float sh[DD];
    __shared__ float s_part[8][HD];
    for (int i = t; i < DD; i += 512) sh[i] = g_hv[((size_t)b * HH + h) * DD + i];
    __syncthreads();

    const int jg = t >> 6;
    const int d  = t & 63;
    float acc = 0.f;
    const float* wp = Wv + h * HD + d;
#pragma unroll 8
    for (int j = jg * 96; j < jg * 96 + 96; j++)
        acc += sh[j] * wp[(size_t)j * DD];
    s_part[jg][d] = acc;
    __syncthreads();
    if (t < HD) {
        float c = bv[h * HD + t];
#pragma unroll
        for (int g = 0; g < 8; g++) c += s_part[g][t];
        g_ctx[b * DD + h * HD + t] = c;
    }
}

// ---------------- 8: new_token = ctx @ Wo + bo  (grid (6,B) x512)
__global__ void k_newtok(const float* __restrict__ Wo, const float* __restrict__ bo,
                         float* __restrict__ out) {
    const int t  = threadIdx.x;
    const int dc = blockIdx.x;
    const int b  = blockIdx.y;
    __shared__ float sc[DD];
    __shared__ float s_part[4][128];
    for (int i = t; i < DD; i += 512) sc[i] = g_ctx[b * DD + i];
    __syncthreads();

    const int jg = t >> 7;
    const int d  = t & 127;
    float acc = 0.f;
    const float* wp = Wo + dc * 128 + d;
#pragma unroll 8
    for (int j = jg * 192; j < jg * 192 + 192; j++)
        acc += sc[j] * wp[(size_t)j * DD];
    s_part[jg][d] = acc;
    __syncthreads();
    if (t < 128) {
        float o = bo[dc * 128 + t] + s_part[0][t] + s_part[1][t] + s_part[2][t] + s_part[3][t];
        out[((size_t)b * KOUT + KSEL) * DD + dc * 128 + t] = o;
    }
}

// ---------------- 9: column-sum of scores (402 MB) grid B*H*4 x256
__global__ void k_reduce_scores(const float* __restrict__ scores,
                                const float* __restrict__ am) {
    const int t   = threadIdx.x;
    const int blk = blockIdx.x;
    const int qc  = blk & 3;
    const int bh  = blk >> 2;
    const int b   = bh / HH;

    __shared__ float s_af[128];
    const int q0 = qc * 128;
    if (t < 128) {
        float amv = am[b * LL + q0 + t];
        s_af[t] = (amv > -10.f) ? 1.f : 0.f;
    }
    __syncthreads();

    const int tq  = t >> 7;
    const int col = t & 127;
    const float4* base =
        (const float4*)(scores + ((size_t)bh * LL + q0 + tq * 64) * LL) + col;
    const float* af = s_af + tq * 64;

    float4 a0 = make_float4(0.f, 0.f, 0.f, 0.f);
#pragma unroll 8
    for (int q = 0; q < 64; q++) {
        const float f = af[q];
        float4 v = __ldcs(base + (size_t)q * (LL / 4));
        a0.x += f * v.x; a0.y += f * v.y;
        a0.z += f * v.z; a0.w += f * v.w;
    }
    float* dst = &g_imp[b * LL + col * 4];
    atomicAdd(dst + 0, a0.x);
    atomicAdd(dst + 1, a0.y);
    atomicAdd(dst + 2, a0.z);
    atomicAdd(dst + 3, a0.w);
}

// ---------------- 10: top-K (exact stable rank + scan)  grid B x512
__global__ void k_topk(const float* __restrict__ am) {
    const int t = threadIdx.x;
    const int b = blockIdx.x;

    __shared__ float sv[LL];
    __shared__ int   ssc[LL];

    const float amv = am[b * LL + t];
    const float afl = (amv > -10.f) ? 1.f : 0.f;
    float v = g_imp[b * LL + t] * afl * (1.0f / (HH * LL));
    if (t == 0) v = CUDART_INF_F;
    sv[t] = v;
    __syncthreads();

    int rank = 0;
#pragma unroll 8
    for (int j = 0; j < LL; j++) {
        float vj = sv[j];
        rank += (vj > v) || (vj == v && j < t);
    }
    const int sel = (rank < KSEL) ? 1 : 0;

    ssc[t] = sel;
    __syncthreads();
    for (int off = 1; off < LL; off <<= 1) {
        int y = (t >= off) ? ssc[t - off] : 0;
        __syncthreads();
        ssc[t] += y;
        __syncthreads();
    }
    if (sel) g_idx[b * KSEL + (ssc[t] - 1)] = t;
}

// ---------------- 11: gather preserved rows + mask  grid (KSEL,B) x192
__global__ void k_gather(const float* __restrict__ hidden, const float* __restrict__ am,
                         float* __restrict__ out) {
    const int t = threadIdx.x;
    const int k = blockIdx.x;
    const int b = blockIdx.y;
    const int idx = g_idx[b * KSEL + k];
    const float4* src = (const float4*)(hidden + ((size_t)b * LL + idx) * DD);
    float4* dst = (float4*)(out + ((size_t)b * KOUT + k) * DD);
    dst[t] = src[t];
    if (t == 0) {
        out[OUT_MASK_OFF + (size_t)b * KOUT + k] = am[b * LL + idx];
    }
}

// ---------------- launcher with (fixed) fork-join overlap ----------------
extern "C" void kernel_launch(void* const* d_in, const int* in_sizes, int n_in,
                              void* d_out, int out_size) {
    const float* hidden = (const float*)d_in[0];
    const float* am     = (const float*)d_in[1];
    const float* scores = (const float*)d_in[2];
    const float* Wq     = (const float*)d_in[3];
    const float* bq     = (const float*)d_in[4];
    const float* Wk     = (const float*)d_in[5];
    const float* bk     = (const float*)d_in[6];
    const float* Wv     = (const float*)d_in[7];
    const float* bv     = (const float*)d_in[8];
    const float* Wo     = (const float*)d_in[9];
    const float* bo     = (const float*)d_in[10];
    float* out = (float*)d_out;

    static cudaStream_t s2 = nullptr;
    static cudaEvent_t ev_fork = nullptr, ev_join = nullptr;
    if (s2 == nullptr) {
        cudaStreamCreateWithFlags(&s2, cudaStreamNonBlocking);
        cudaEventCreateWithFlags(&ev_fork, cudaEventDisableTiming);
        cudaEventCreateWithFlags(&ev_join, cudaEventDisableTiming);
    }

    k_prologue<<<64, 512>>>(am, out);                           // #1 (stream 0)

    // FORK: event records dependencies = prologue ONLY (recorded before chain enqueue)
    cudaEventRecord(ev_fork, 0);
    cudaStreamWaitEvent(s2, ev_fork, 0);

    // main chain (stream 0)
    {
        dim3 g(6, 8, BB);
        k_sentence<<<g, 128>>>(hidden);                         // #2
    }
    {
        dim3 g(HH, BB);
        k_qk<<<g, 512>>>(Wq, bq, Wk, bk);                       // #3
    }
    {
        dim3 g(32, BB);
        k_logits<<<g, 384>>>(hidden, am);                       // #4 (profiled)
    }
    k_softmax_w<<<BB * HH, 512>>>();                            // #5
    {
        dim3 g(6, 8, BB);
        k_hv<<<g, 128>>>(hidden);                               // #6
    }
    {
        dim3 g(HH, BB);
        k_ctx<<<g, 512>>>(Wv, bv);                              // #7
    }
    {
        dim3 g(6, BB);
        k_newtok<<<g, 512>>>(Wo, bo, out);                      // #8
    }

    // importance branch (s2) — depends only on prologue via ev_fork
    k_reduce_scores<<<BB * HH * 4, 256, 0, s2>>>(scores, am);   // #9
    k_topk<<<BB, 512, 0, s2>>>(am);                             // #10
    {
        dim3 g(KSEL, BB);
        k_gather<<<g, 192, 0, s2>>>(hidden, am, out);           // #11
    }

    // JOIN
    cudaEventRecord(ev_join, s2);
    cudaStreamWaitEvent(0, ev_join, 0);
}